// round 9
// baseline (speedup 1.0000x reference)
#include <cuda_runtime.h>
#include <cuda_bf16.h>

// SosModel: 4-section cascaded biquad along T of x[B,T,C].
// Overlap-save chunking + DF2T sections + packed f32x2 FMA (Blackwell FFMA2).
// Each thread carries TWO adjacent channels in one 64-bit register (one warp
// covers all 64 channels of a (batch, chunk)); loads/stores are 64-bit
// -> one 256B transaction per warp per timestep.
//
// R9: single ROTATING prefetch buffer instead of double buffer:
//   v = buf[i]; buf[i] = load(one block ahead); step(v);
// Prefetch distance is still a full block (U steps), but buffer cost is
// U regs instead of 2U -> ~60 regs -> 8 blocks/SM -> ALL 1024 blocks
// resident in one wave with a 16-deep load pipeline per warp
// (R7 showed U=16 wins; R8 showed full residency wins; this gets both).

#define BB 16
#define TT 32768
#define CC 64
#define SS 4
#define CHUNK_L 128
#define WARM_W 64               // max pole radius ~0.755 -> 0.755^64 ~ 1.5e-8
#define NCHUNK (TT / CHUNK_L)   // 256
#define U 16                    // prefetch pipeline depth (single buffer)

typedef unsigned long long u64v;

__device__ __forceinline__ u64v dup2(float v) {
    u64v r;
    asm("mov.b64 %0, {%1, %1};" : "=l"(r) : "f"(v));
    return r;
}

#define FMA2(d, a, b, c) \
    asm("fma.rn.f32x2 %0, %1, %2, %3;" : "=l"(d) : "l"(a), "l"(b), "l"(c))
#define MUL2(d, a, b) \
    asm("mul.rn.f32x2 %0, %1, %2;" : "=l"(d) : "l"(a), "l"(b))

__global__ __launch_bounds__(128)
void sos_biquad_kernel(const float* __restrict__ x,
                       const float* __restrict__ sos,
                       float* __restrict__ out)
{
    const int gtid = blockIdx.x * blockDim.x + threadIdx.x;
    const int gw   = gtid >> 5;          // warp id: [0, BB*NCHUNK)
    const int lane = gtid & 31;

    const int chunk = gw % NCHUNK;
    const int b     = gw / NCHUNK;

    // Normalized, duplicated coefficients (a1/a2 negated -> pure FMA loop).
    u64v cb0[SS], cb1[SS], cb2[SS], na1[SS], na2[SS];
#pragma unroll
    for (int s = 0; s < SS; s++) {
        const float v0 = __ldg(&sos[s * 6 + 0]);
        const float v1 = __ldg(&sos[s * 6 + 1]);
        const float v2 = __ldg(&sos[s * 6 + 2]);
        const float a0 = __ldg(&sos[s * 6 + 3]);
        const float a1 = __ldg(&sos[s * 6 + 4]);
        const float a2 = __ldg(&sos[s * 6 + 5]);
        const float inv = 1.0f / a0;
        cb0[s] = dup2(v0 * inv);
        cb1[s] = dup2(v1 * inv);
        cb2[s] = dup2(v2 * inv);
        na1[s] = dup2(-a1 * inv);
        na2[s] = dup2(-a2 * inv);
    }

    // DF2T state (packed): y = b0*x + s1 ; s1 = b1*x - a1*y + s2 ; s2 = b2*x - a2*y
    u64v st1[SS], st2[SS];
#pragma unroll
    for (int s = 0; s < SS; s++) { st1[s] = 0ull; st2[s] = 0ull; }

    const int t0     = chunk * CHUNK_L;
    const int tstart = (chunk == 0) ? 0 : (t0 - WARM_W);
    const int nwarm  = (t0 - tstart) / U;      // 0 or 4 warm-up blocks

    // Thread lane handles channels (2*lane, 2*lane+1) packed -> u64 pointers,
    // per-timestep stride = CC/2 = 32 u64 elements.
    const size_t base = (size_t)b * TT * CC + (size_t)2 * lane;
    const u64v* __restrict__ xp =
        (const u64v*)(x + base + (size_t)tstart * CC);
    u64v* __restrict__ op = (u64v*)(out + base + (size_t)t0 * CC);

#define SOS_STEP(v)                                   \
    do {                                              \
        _Pragma("unroll")                             \
        for (int s = 0; s < SS; s++) {                \
            u64v y, t1, t2;                           \
            FMA2(y,  cb0[s], (v), st1[s]);            \
            FMA2(t1, cb1[s], (v), st2[s]);            \
            MUL2(t2, cb2[s], (v));                    \
            FMA2(st1[s], na1[s], y, t1);              \
            FMA2(st2[s], na2[s], y, t2);              \
            (v) = y;                                  \
        }                                             \
    } while (0)

    // Prologue: fill the rotating buffer with block 0.
    u64v buf[U];
#pragma unroll
    for (int i = 0; i < U; i++) buf[i] = __ldg(&xp[(size_t)i * 32]);

    // Warm-up blocks: consume buf[i], immediately refill from one block
    // ahead, run the recurrence without storing.
#pragma unroll 1
    for (int blk = 0; blk < nwarm; blk++) {
#pragma unroll
        for (int i = 0; i < U; i++) {
            u64v v = buf[i];
            buf[i] = __ldg(&xp[(size_t)(U + i) * 32]);
            SOS_STEP(v);
        }
        xp += (size_t)U * 32;
    }

    // Payload blocks except the last: consume + refill + store.
#pragma unroll 1
    for (int blk = 0; blk < CHUNK_L / U - 1; blk++) {
#pragma unroll
        for (int i = 0; i < U; i++) {
            u64v v = buf[i];
            buf[i] = __ldg(&xp[(size_t)(U + i) * 32]);
            SOS_STEP(v);
            op[(size_t)i * 32] = v;
        }
        xp += (size_t)U * 32;
        op += (size_t)U * 32;
    }

    // Last payload block: no refill (would read past T).
#pragma unroll
    for (int i = 0; i < U; i++) {
        u64v v = buf[i];
        SOS_STEP(v);
        op[(size_t)i * 32] = v;
    }
#undef SOS_STEP
}

extern "C" void kernel_launch(void* const* d_in, const int* in_sizes, int n_in,
                              void* d_out, int out_size)
{
    const float* x   = (const float*)d_in[0];
    const float* sos = (const float*)d_in[1];
    float* out = (float*)d_out;

    const int total_warps = BB * NCHUNK;              // 4096
    const int threads = 128;
    const int blocks = (total_warps * 32) / threads;  // 1024

    sos_biquad_kernel<<<blocks, threads>>>(x, sos, out);
}

// round 10
// speedup vs baseline: 1.0011x; 1.0011x over previous
#include <cuda_runtime.h>
#include <cuda_bf16.h>

// SosModel: 4-section cascaded biquad along T of x[B,T,C].
// Overlap-save chunking + DF2T + packed f32x2 FMA.
//
// R10: 4 channels/thread, 2 sequences/warp (lanes 0-15 = seq A, 16-31 =
// seq B, same chunk so no divergence). Memory ops become LDG.128/STG.128,
// halving LSU occupancy (~26us -> ~16us per SM), which was capping DRAM%
// at ~70%. FMA warp-ops unchanged; two independent chains/thread add ILP.
// U=8 double buffer keeps 8MB of loads in flight chip-wide.

#define BB 16
#define TT 32768
#define CC 64
#define SS 4
#define CHUNK_L 128
#define WARM_W 64               // max pole radius ~0.755 -> 0.755^64 ~ 1.5e-8
#define NCHUNK (TT / CHUNK_L)   // 256
#define U 8                     // pipeline depth (double buffer)

typedef unsigned long long u64v;

__device__ __forceinline__ u64v dup2(float v) {
    u64v r;
    asm("mov.b64 %0, {%1, %1};" : "=l"(r) : "f"(v));
    return r;
}

#define FMA2(d, a, b, c) \
    asm("fma.rn.f32x2 %0, %1, %2, %3;" : "=l"(d) : "l"(a), "l"(b), "l"(c))
#define MUL2(d, a, b) \
    asm("mul.rn.f32x2 %0, %1, %2;" : "=l"(d) : "l"(a), "l"(b))

__global__ __launch_bounds__(128, 4)
void sos_biquad_kernel(const float* __restrict__ x,
                       const float* __restrict__ sos,
                       float* __restrict__ out)
{
    const int gtid = blockIdx.x * blockDim.x + threadIdx.x;
    const int gw   = gtid >> 5;          // warp id: [0, 2048)
    const int lane = gtid & 31;

    const int chunk = gw & (NCHUNK - 1);       // same chunk for whole warp
    const int bp    = gw >> 8;                 // batch pair 0..7
    const int half  = lane >> 4;               // 0: seq A, 1: seq B
    const int b     = bp * 2 + half;
    const int cl    = lane & 15;               // channel group: 4*cl..4*cl+3

    // Normalized, duplicated coefficients (a1/a2 negated -> pure FMA loop).
    u64v cb0[SS], cb1[SS], cb2[SS], na1[SS], na2[SS];
#pragma unroll
    for (int s = 0; s < SS; s++) {
        const float v0 = __ldg(&sos[s * 6 + 0]);
        const float v1 = __ldg(&sos[s * 6 + 1]);
        const float v2 = __ldg(&sos[s * 6 + 2]);
        const float a0 = __ldg(&sos[s * 6 + 3]);
        const float a1 = __ldg(&sos[s * 6 + 4]);
        const float a2 = __ldg(&sos[s * 6 + 5]);
        const float inv = 1.0f / a0;
        cb0[s] = dup2(v0 * inv);
        cb1[s] = dup2(v1 * inv);
        cb2[s] = dup2(v2 * inv);
        na1[s] = dup2(-a1 * inv);
        na2[s] = dup2(-a2 * inv);
    }

    // DF2T state for 2 channel-pairs (x,y halves of the float4).
    u64v s1x[SS], s2x[SS], s1y[SS], s2y[SS];
#pragma unroll
    for (int s = 0; s < SS; s++) {
        s1x[s] = 0ull; s2x[s] = 0ull; s1y[s] = 0ull; s2y[s] = 0ull;
    }

    const int t0     = chunk * CHUNK_L;
    const int tstart = (chunk == 0) ? 0 : (t0 - WARM_W);
    const int nwarm  = (t0 - tstart) / U;      // 0 or 8 warm-up blocks

    // 16B per thread per timestep; stride per t = CC*4B/16 = 16 ulonglong2.
    const size_t base = (size_t)b * TT * CC + (size_t)4 * cl;
    const ulonglong2* __restrict__ xp =
        (const ulonglong2*)(x + base) + (size_t)tstart * 16;
    ulonglong2* __restrict__ op =
        (ulonglong2*)(out + base) + (size_t)t0 * 16;

    // One section cascade applied to one packed pair (u64 = 2 channels).
#define SOS_ONE(v, s1, s2)                            \
    do {                                              \
        _Pragma("unroll")                             \
        for (int s = 0; s < SS; s++) {                \
            u64v y, t1, t2;                           \
            FMA2(y,  cb0[s], (v), s1[s]);             \
            FMA2(t1, cb1[s], (v), s2[s]);             \
            MUL2(t2, cb2[s], (v));                    \
            FMA2(s1[s], na1[s], y, t1);               \
            FMA2(s2[s], na2[s], y, t2);               \
            (v) = y;                                  \
        }                                             \
    } while (0)

#define SOS_STEP2(vv)                                 \
    do {                                              \
        SOS_ONE((vv).x, s1x, s2x);                    \
        SOS_ONE((vv).y, s1y, s2y);                    \
    } while (0)

    // Pipeline prologue: preload first block.
    ulonglong2 buf[U];
#pragma unroll
    for (int i = 0; i < U; i++) buf[i] = xp[(size_t)i * 16];
    xp += (size_t)U * 16;

    // Warm-up blocks: compute state only, prefetch next block meanwhile.
#pragma unroll 1
    for (int blk = 0; blk < nwarm; blk++) {
        ulonglong2 nbuf[U];
#pragma unroll
        for (int i = 0; i < U; i++) nbuf[i] = xp[(size_t)i * 16];
        xp += (size_t)U * 16;
#pragma unroll
        for (int i = 0; i < U; i++) {
            ulonglong2 v = buf[i];
            SOS_STEP2(v);
        }
#pragma unroll
        for (int i = 0; i < U; i++) buf[i] = nbuf[i];
    }

    // Payload blocks except the last: prefetch + compute + store.
#pragma unroll 1
    for (int blk = 0; blk < CHUNK_L / U - 1; blk++) {
        ulonglong2 nbuf[U];
#pragma unroll
        for (int i = 0; i < U; i++) nbuf[i] = xp[(size_t)i * 16];
        xp += (size_t)U * 16;
#pragma unroll
        for (int i = 0; i < U; i++) {
            ulonglong2 v = buf[i];
            SOS_STEP2(v);
            op[(size_t)i * 16] = v;
        }
        op += (size_t)U * 16;
#pragma unroll
        for (int i = 0; i < U; i++) buf[i] = nbuf[i];
    }

    // Last payload block: no prefetch (would read past T).
#pragma unroll
    for (int i = 0; i < U; i++) {
        ulonglong2 v = buf[i];
        SOS_STEP2(v);
        op[(size_t)i * 16] = v;
    }
#undef SOS_STEP2
#undef SOS_ONE
}

extern "C" void kernel_launch(void* const* d_in, const int* in_sizes, int n_in,
                              void* d_out, int out_size)
{
    const float* x   = (const float*)d_in[0];
    const float* sos = (const float*)d_in[1];
    float* out = (float*)d_out;

    const int total_warps = (BB / 2) * NCHUNK;        // 2048 (2 seqs/warp)
    const int threads = 128;
    const int blocks = (total_warps * 32) / threads;  // 512

    sos_biquad_kernel<<<blocks, threads>>>(x, sos, out);
}

// round 11
// speedup vs baseline: 1.1370x; 1.1358x over previous
#include <cuda_runtime.h>
#include <cuda_bf16.h>

// SosModel: 4-section cascaded biquad along T of x[B,T,C].
// Overlap-save chunking + DF2T + packed f32x2 FMA (FFMA2), 2 channels/thread,
// one warp = one (batch, chunk): 256B coalesced warp transactions.
//
// R11 synthesis of R6-R10 findings:
//  * ncu time tracks in-flight load bytes -> want U=16 pipeline depth.
//  * e2e penalizes multi-wave launches (+9us vs +4us over ncu) -> need
//    blocks <= 5/SM*148 = 740 at the 90-reg cost of U=16.
//  * => CHUNK_L=256 (2048 warps, 512 blocks, single wave) + WARM_W=64
//    (work factor 1.25; max pole radius ~0.755 -> truncation ~1.5e-8).

#define BB 16
#define TT 32768
#define CC 64
#define SS 4
#define CHUNK_L 256
#define WARM_W 64
#define NCHUNK (TT / CHUNK_L)   // 128
#define U 16                    // pipeline depth (double buffer)

typedef unsigned long long u64v;

__device__ __forceinline__ u64v dup2(float v) {
    u64v r;
    asm("mov.b64 %0, {%1, %1};" : "=l"(r) : "f"(v));
    return r;
}

#define FMA2(d, a, b, c) \
    asm("fma.rn.f32x2 %0, %1, %2, %3;" : "=l"(d) : "l"(a), "l"(b), "l"(c))
#define MUL2(d, a, b) \
    asm("mul.rn.f32x2 %0, %1, %2;" : "=l"(d) : "l"(a), "l"(b))

__global__ __launch_bounds__(128)
void sos_biquad_kernel(const float* __restrict__ x,
                       const float* __restrict__ sos,
                       float* __restrict__ out)
{
    const int gtid = blockIdx.x * blockDim.x + threadIdx.x;
    const int gw   = gtid >> 5;          // warp id: [0, BB*NCHUNK)
    const int lane = gtid & 31;

    const int chunk = gw & (NCHUNK - 1);
    const int b     = gw >> 7;           // gw / NCHUNK

    // Normalized, duplicated coefficients (a1/a2 negated -> pure FMA loop).
    // Warp-uniform -> ptxas keeps them in UR, not the per-thread regfile.
    u64v cb0[SS], cb1[SS], cb2[SS], na1[SS], na2[SS];
#pragma unroll
    for (int s = 0; s < SS; s++) {
        const float v0 = __ldg(&sos[s * 6 + 0]);
        const float v1 = __ldg(&sos[s * 6 + 1]);
        const float v2 = __ldg(&sos[s * 6 + 2]);
        const float a0 = __ldg(&sos[s * 6 + 3]);
        const float a1 = __ldg(&sos[s * 6 + 4]);
        const float a2 = __ldg(&sos[s * 6 + 5]);
        const float inv = 1.0f / a0;
        cb0[s] = dup2(v0 * inv);
        cb1[s] = dup2(v1 * inv);
        cb2[s] = dup2(v2 * inv);
        na1[s] = dup2(-a1 * inv);
        na2[s] = dup2(-a2 * inv);
    }

    // DF2T state (packed): y = b0*x + s1 ; s1 = b1*x - a1*y + s2 ; s2 = b2*x - a2*y
    u64v st1[SS], st2[SS];
#pragma unroll
    for (int s = 0; s < SS; s++) { st1[s] = 0ull; st2[s] = 0ull; }

    const int t0     = chunk * CHUNK_L;
    const int tstart = (chunk == 0) ? 0 : (t0 - WARM_W);
    const int nwarm  = (t0 - tstart) / U;      // 0 or 4 warm-up blocks

    // Thread lane handles channels (2*lane, 2*lane+1) packed -> u64 pointers,
    // per-timestep stride = CC/2 = 32 u64 elements.
    const size_t base = (size_t)b * TT * CC + (size_t)2 * lane;
    const u64v* __restrict__ xp =
        (const u64v*)(x + base) + (size_t)tstart * 32;
    u64v* __restrict__ op =
        (u64v*)(out + base) + (size_t)t0 * 32;

#define SOS_STEP(v)                                   \
    do {                                              \
        _Pragma("unroll")                             \
        for (int s = 0; s < SS; s++) {                \
            u64v y, t1, t2;                           \
            FMA2(y,  cb0[s], (v), st1[s]);            \
            FMA2(t1, cb1[s], (v), st2[s]);            \
            MUL2(t2, cb2[s], (v));                    \
            FMA2(st1[s], na1[s], y, t1);              \
            FMA2(st2[s], na2[s], y, t2);              \
            (v) = y;                                  \
        }                                             \
    } while (0)

    // Pipeline prologue: preload first block.
    u64v buf[U];
#pragma unroll
    for (int i = 0; i < U; i++) buf[i] = __ldg(&xp[(size_t)i * 32]);
    xp += (size_t)U * 32;

    // Warm-up blocks: compute state only, prefetch next block meanwhile.
#pragma unroll 1
    for (int blk = 0; blk < nwarm; blk++) {
        u64v nbuf[U];
#pragma unroll
        for (int i = 0; i < U; i++) nbuf[i] = __ldg(&xp[(size_t)i * 32]);
        xp += (size_t)U * 32;
#pragma unroll
        for (int i = 0; i < U; i++) {
            u64v v = buf[i];
            SOS_STEP(v);
        }
#pragma unroll
        for (int i = 0; i < U; i++) buf[i] = nbuf[i];
    }

    // Payload blocks except the last: prefetch + compute + store.
#pragma unroll 1
    for (int blk = 0; blk < CHUNK_L / U - 1; blk++) {
        u64v nbuf[U];
#pragma unroll
        for (int i = 0; i < U; i++) nbuf[i] = __ldg(&xp[(size_t)i * 32]);
        xp += (size_t)U * 32;
#pragma unroll
        for (int i = 0; i < U; i++) {
            u64v v = buf[i];
            SOS_STEP(v);
            op[(size_t)i * 32] = v;
        }
        op += (size_t)U * 32;
#pragma unroll
        for (int i = 0; i < U; i++) buf[i] = nbuf[i];
    }

    // Last payload block: no prefetch (would read past T).
#pragma unroll
    for (int i = 0; i < U; i++) {
        u64v v = buf[i];
        SOS_STEP(v);
        op[(size_t)i * 32] = v;
    }
#undef SOS_STEP
}

extern "C" void kernel_launch(void* const* d_in, const int* in_sizes, int n_in,
                              void* d_out, int out_size)
{
    const float* x   = (const float*)d_in[0];
    const float* sos = (const float*)d_in[1];
    float* out = (float*)d_out;

    const int total_warps = BB * NCHUNK;              // 2048
    const int threads = 128;
    const int blocks = (total_warps * 32) / threads;  // 512 (single wave)

    sos_biquad_kernel<<<blocks, threads>>>(x, sos, out);
}